// round 9
// baseline (speedup 1.0000x reference)
#include <cuda_runtime.h>
#include <math.h>

// Problem constants (fixed by the reference)
#define S_LEN   1024
#define I_DIM   1024
#define H_DIM   2048
#define L_NUM   4

#define SCAN_CTAS     128
#define ROWS_PER_CTA  16              // H_DIM / SCAN_CTAS
#define SCAN_THREADS  128             // 4 warps, 4 rows per warp
#define SCAN_SMEM_BYTES (ROWS_PER_CTA * H_DIM * (int)sizeof(float))  // 131072 (weights only)
#define CNT_STRIDE 64                 // 256B stride: varies LTS hash bit 8 (bit 7 is
                                      // transparent, so 128B kept all counters on ONE slice)
#define ARRIVALS_PER_STEP (SCAN_CTAS * 4)   // one red per warp per CTA = 512

// Scratch (device globals — no allocation allowed)
__device__ float g_U [S_LEN * H_DIM];            // u_l(t) for current layer (8 MB)
__device__ float g_HA[S_LEN * H_DIM];            // hidden states of current layer (8 MB)
__device__ int   g_cnt[S_LEN * CNT_STRIDE];      // strided per-timestep arrival counters

// ---------------------------------------------------------------------------
// Sync helpers.
// RULE (learned from R4/R7/R8 failures vs R2/R5/R6 passes): the arrival
// counter must be polled with MORALLY STRONG loads. A weak ld.cg racing with
// red.release.gpu is a data race in the PTX model — no synchronizes-with edge
// forms and the subsequent weak h loads may be stale. ld.relaxed.gpu +
// fence.acq_rel.gpu on success is the R5-proven passing pattern.
// Producer chain (R6-proven): same thread does st.cg of its rows then
// red.release.gpu — program order makes the release cover the stores.
// ---------------------------------------------------------------------------
__device__ __forceinline__ int ld_relaxed_gpu(const int* p) {
    int v;
    asm volatile("ld.relaxed.gpu.global.s32 %0, [%1];" : "=r"(v) : "l"(p) : "memory");
    return v;
}
__device__ __forceinline__ void fence_gpu() {
    asm volatile("fence.acq_rel.gpu;" ::: "memory");
}
__device__ __forceinline__ void red_release_gpu(int* p) {
    asm volatile("red.release.gpu.global.add.s32 [%0], 1;" :: "l"(p) : "memory");
}

// ---------------------------------------------------------------------------
// GEMM: C[M,N] = A[M,K] @ B[N,K]^T + bias1[n] + bias2[n]
// 128x128 tile, BK=8, 256 threads, 8x8 per-thread microtile. (Proven; unchanged.)
// ---------------------------------------------------------------------------
__global__ void gemm_bias_kernel(const float* __restrict__ A,
                                 const float* __restrict__ B,
                                 float* __restrict__ C,
                                 const float* __restrict__ bias1,
                                 const float* __restrict__ bias2,
                                 int M, int N, int K)
{
    __shared__ float As[8][128];
    __shared__ float Bs[8][128];

    const int tid = threadIdx.x;
    const int bm  = blockIdx.y * 128;
    const int bn  = blockIdx.x * 128;

    const int loadRow = tid >> 1;        // 0..127
    const int loadCol = (tid & 1) * 4;   // 0 or 4

    const int tx = tid & 15;             // n sub-tile
    const int ty = tid >> 4;             // m sub-tile

    float acc[8][8];
#pragma unroll
    for (int i = 0; i < 8; i++)
#pragma unroll
        for (int j = 0; j < 8; j++) acc[i][j] = 0.f;

    const float* Ag = A + (size_t)(bm + loadRow) * K + loadCol;
    const float* Bg = B + (size_t)(bn + loadRow) * K + loadCol;

    for (int k0 = 0; k0 < K; k0 += 8) {
        float4 av = *(const float4*)(Ag + k0);
        float4 bv = *(const float4*)(Bg + k0);
        As[loadCol + 0][loadRow] = av.x;
        As[loadCol + 1][loadRow] = av.y;
        As[loadCol + 2][loadRow] = av.z;
        As[loadCol + 3][loadRow] = av.w;
        Bs[loadCol + 0][loadRow] = bv.x;
        Bs[loadCol + 1][loadRow] = bv.y;
        Bs[loadCol + 2][loadRow] = bv.z;
        Bs[loadCol + 3][loadRow] = bv.w;
        __syncthreads();

#pragma unroll
        for (int k = 0; k < 8; k++) {
            float a[8], b[8];
#pragma unroll
            for (int i = 0; i < 8; i++) a[i] = As[k][ty * 8 + i];
#pragma unroll
            for (int j = 0; j < 8; j++) b[j] = Bs[k][tx * 8 + j];
#pragma unroll
            for (int i = 0; i < 8; i++)
#pragma unroll
                for (int j = 0; j < 8; j++)
                    acc[i][j] += a[i] * b[j];
        }
        __syncthreads();
    }

    // Epilogue with fused bias add, float4 stores
#pragma unroll
    for (int i = 0; i < 8; i++) {
        const int m = bm + ty * 8 + i;
        float* crow = C + (size_t)m * N + bn + tx * 8;
#pragma unroll
        for (int j = 0; j < 8; j += 4) {
            const int n = bn + tx * 8 + j;
            float4 v;
            v.x = acc[i][j + 0] + bias1[n + 0] + bias2[n + 0];
            v.y = acc[i][j + 1] + bias1[n + 1] + bias2[n + 1];
            v.z = acc[i][j + 2] + bias1[n + 2] + bias2[n + 2];
            v.w = acc[i][j + 3] + bias1[n + 3] + bias2[n + 3];
            *(float4*)(crow + j) = v;
        }
    }
}

// ---------------------------------------------------------------------------
// Persistent scan: h(t) = tanh(U[t] + Wh @ h(t-1)) over t = 0..S-1.
// Wh (H x H) sliced across 128 CTAs' SMEM (16 rows each, 4 rows per warp).
// Per step, per warp (no intra-CTA barriers, no relay):
//   wait:   EVERY warp polls cnt[t-1] with ld.relaxed.gpu (4 phase-offset
//           samplers per CTA cut detection latency ~4x vs one), then one
//           fence.acq_rel.gpu. All lanes hit the same address -> one L2
//           request per warp per probe.
//   load:   h(t-1) streamed from L2 via depth-8 __ldcg register pipeline.
//   commit: lane0 stores its warp's 4 rows (st.cg.v4) then red.release.gpu
//           on cnt[t] (release in the storing thread). 512 arrivals/step.
// ---------------------------------------------------------------------------
__global__ void __launch_bounds__(SCAN_THREADS, 1)
scan_kernel(const float* __restrict__ Wh,    // layer's H x H row-major slice base
            const float* __restrict__ U,     // S x H (biases already folded in)
            float* __restrict__ Hout,        // S x H; reads t-1, writes t
            int* cnt,                        // strided arrival counters
            int wait_target)                 // 512*(layer+1)
{
    extern __shared__ float smem[];
    float* sW = smem;                         // ROWS_PER_CTA * H_DIM floats

    const int tid  = threadIdx.x;
    const int lane = tid & 31;
    const int warp = tid >> 5;
    const int row0 = blockIdx.x * ROWS_PER_CTA;

    // Stage this CTA's 16 weight rows into SMEM (contiguous rows, coalesced)
    {
        const float4* Wg  = (const float4*)(Wh + (size_t)row0 * H_DIM);
        float4* sW4 = (float4*)sW;
        const int nvec = ROWS_PER_CTA * H_DIM / 4;
        for (int i = tid; i < nvec; i += SCAN_THREADS) sW4[i] = Wg[i];
    }
    __syncthreads();

    const float4* w0 = (const float4*)(sW + (warp * 4 + 0) * H_DIM);
    const float4* w1 = (const float4*)(sW + (warp * 4 + 1) * H_DIM);
    const float4* w2 = (const float4*)(sW + (warp * 4 + 2) * H_DIM);
    const float4* w3 = (const float4*)(sW + (warp * 4 + 3) * H_DIM);

    const int gr0 = row0 + warp * 4;          // this warp's first output row

    for (int t = 0; t < S_LEN; t++) {
        // U is stable data (from the preceding GEMM) — prefetch before wait
        float4 uv;
        if (lane == 0) uv = __ldg((const float4*)(U + (size_t)t * H_DIM + gr0));

        float a0 = 0.f, a1 = 0.f, a2 = 0.f, a3 = 0.f;

        if (t > 0) {
            // Morally-strong probe (R5-proven); every warp samples directly.
            const int* cp = cnt + (size_t)(t - 1) * CNT_STRIDE;
            while (ld_relaxed_gpu(cp) < wait_target) { }
            fence_gpu();

            // h(t-1): depth-8 register-rolling __ldcg pipeline
            const float4* hp4 = (const float4*)(Hout + (size_t)(t - 1) * H_DIM);
            float4 hb[8];
#pragma unroll
            for (int p = 0; p < 8; p++) hb[p] = __ldcg(hp4 + lane + 32 * p);

#pragma unroll
            for (int i = 0; i < H_DIM / 128; i++) {     // 16 iterations
                const int idx = lane + 32 * i;
                float4 hv = hb[i & 7];
                if (i + 8 < H_DIM / 128)
                    hb[i & 7] = __ldcg(hp4 + idx + 32 * 8);
                float4 x0 = w0[idx];
                float4 x1 = w1[idx];
                float4 x2 = w2[idx];
                float4 x3 = w3[idx];
                a0 += x0.x * hv.x + x0.y * hv.y + x0.z * hv.z + x0.w * hv.w;
                a1 += x1.x * hv.x + x1.y * hv.y + x1.z * hv.z + x1.w * hv.w;
                a2 += x2.x * hv.x + x2.y * hv.y + x2.z * hv.z + x2.w * hv.w;
                a3 += x3.x * hv.x + x3.y * hv.y + x3.z * hv.z + x3.w * hv.w;
            }
#pragma unroll
            for (int off = 16; off > 0; off >>= 1) {
                a0 += __shfl_xor_sync(0xffffffffu, a0, off);
                a1 += __shfl_xor_sync(0xffffffffu, a1, off);
                a2 += __shfl_xor_sync(0xffffffffu, a2, off);
                a3 += __shfl_xor_sync(0xffffffffu, a3, off);
            }
        }

        // lane0 holds all four reduced sums: one st.cg.v4 + release-red arrive
        // (release in the SAME thread as the store — R6-proven ordering).
        if (lane == 0) {
            float4 hv;
            hv.x = tanhf(uv.x + a0);
            hv.y = tanhf(uv.y + a1);
            hv.z = tanhf(uv.z + a2);
            hv.w = tanhf(uv.w + a3);
            __stcg((float4*)(Hout + (size_t)t * H_DIM + gr0), hv);
            red_release_gpu(cnt + (size_t)t * CNT_STRIDE);
        }
    }
}

// ---------------------------------------------------------------------------
extern "C" void kernel_launch(void* const* d_in, const int* in_sizes, int n_in,
                              void* d_out, int out_size)
{
    const float* input = (const float*)d_in[0];   // (1, S, I)
    const float* Wi0   = (const float*)d_in[1];   // (H, I)
    const float* bi0   = (const float*)d_in[2];   // (H)
    const float* WiR   = (const float*)d_in[3];   // (L-1, H, H)
    const float* biR   = (const float*)d_in[4];   // (L-1, H)
    const float* Wh    = (const float*)d_in[5];   // (L, H, H)
    const float* bh    = (const float*)d_in[6];   // (L, H)
    float* out = (float*)d_out;                   // (S, 1, H) contiguous

    float *U, *HA; int* cnt;
    cudaGetSymbolAddress((void**)&U,  g_U);
    cudaGetSymbolAddress((void**)&HA, g_HA);
    cudaGetSymbolAddress((void**)&cnt, g_cnt);

    cudaFuncSetAttribute(scan_kernel,
                         cudaFuncAttributeMaxDynamicSharedMemorySize,
                         SCAN_SMEM_BYTES);

    // Counters must be zero at the start of every replay (graph-captured node)
    cudaMemsetAsync(cnt, 0, S_LEN * CNT_STRIDE * sizeof(int));

    dim3 gemm_grid(H_DIM / 128, S_LEN / 128);   // (16, 8)

    // Layer 0: U = X @ Wi0^T + bi0 + bh[0]; then scan with Wh[0]
    gemm_bias_kernel<<<gemm_grid, 256>>>(input, Wi0, U, bi0, bh, S_LEN, H_DIM, I_DIM);
    scan_kernel<<<SCAN_CTAS, SCAN_THREADS, SCAN_SMEM_BYTES>>>(Wh, U, HA, cnt,
                                                              ARRIVALS_PER_STEP);

    // Layers 1..3
    for (int l = 1; l < L_NUM; l++) {
        const float* Wi_l = WiR + (size_t)(l - 1) * H_DIM * H_DIM;
        const float* bi_l = biR + (size_t)(l - 1) * H_DIM;
        const float* Wh_l = Wh  + (size_t)l * H_DIM * H_DIM;
        const float* bh_l = bh  + (size_t)l * H_DIM;
        float* dst = (l == L_NUM - 1) ? out : HA;

        gemm_bias_kernel<<<gemm_grid, 256>>>(HA, Wi_l, U, bi_l, bh_l,
                                             S_LEN, H_DIM, H_DIM);
        scan_kernel<<<SCAN_CTAS, SCAN_THREADS, SCAN_SMEM_BYTES>>>(Wh_l, U, dst, cnt,
                                                                  ARRIVALS_PER_STEP * (l + 1));
    }
}

// round 10
// speedup vs baseline: 1.0109x; 1.0109x over previous
#include <cuda_runtime.h>
#include <math.h>

// Problem constants (fixed by the reference)
#define S_LEN   1024
#define I_DIM   1024
#define H_DIM   2048
#define L_NUM   4

#define SCAN_CTAS     128
#define ROWS_PER_CTA  16              // H_DIM / SCAN_CTAS
#define SCAN_THREADS  128             // 4 warps, 4 rows per warp
#define SCAN_SMEM_BYTES (ROWS_PER_CTA * H_DIM * (int)sizeof(float))  // 131072 (weights only)
#define CNT_STRIDE 128                // ints per step: LO at +0, HI at +64 (256B apart
                                      // -> different LTS slice; bit 7 is transparent)
#define HALF_ARRIVALS 256             // 64 CTAs x 4 warps per half per layer

// Scratch (device globals — no allocation allowed)
__device__ float g_U [S_LEN * H_DIM];            // u_l(t) for current layer (8 MB)
__device__ float g_HA[S_LEN * H_DIM];            // hidden states of current layer (8 MB)
__device__ int   g_cnt[S_LEN * CNT_STRIDE];      // per-step split arrival counters

// ---------------------------------------------------------------------------
// Sync rules learned this session (R4/R7/R8 fails vs R2/R5/R6/R9 passes):
//  1. Poll ONLY with morally-strong loads (ld.relaxed/ld.acquire). A weak
//     ld.cg racing red.release is a data race -> stale h. (3 failures)
//  2. Minimize concurrent global spinners: all-warp spinning costs ~1200
//     cyc/step vs one-warp+SMEM-relay (R9/R5 = 15.1ms vs R6 = 12.3ms).
// Producer chain (R6-proven): same thread does st.cg then red.release.gpu.
// Consumer LO: warp0 ld.acquire spin + st.release.cta relay (R6-proven).
// Consumer HI: single early ld.relaxed probe issued BEFORE first-half
//             compute + fence on success (R5-proven pattern); spin fallback.
// ---------------------------------------------------------------------------
__device__ __forceinline__ int ld_relaxed_gpu(const int* p) {
    int v;
    asm volatile("ld.relaxed.gpu.global.s32 %0, [%1];" : "=r"(v) : "l"(p) : "memory");
    return v;
}
__device__ __forceinline__ int ld_acquire_gpu(const int* p) {
    int v;
    asm volatile("ld.acquire.gpu.global.s32 %0, [%1];" : "=r"(v) : "l"(p) : "memory");
    return v;
}
__device__ __forceinline__ void fence_gpu() {
    asm volatile("fence.acq_rel.gpu;" ::: "memory");
}
__device__ __forceinline__ void red_release_gpu(int* p) {
    asm volatile("red.release.gpu.global.add.s32 [%0], 1;" :: "l"(p) : "memory");
}
__device__ __forceinline__ void st_release_shared(int* p, int v) {
    unsigned a = (unsigned)__cvta_generic_to_shared(p);
    asm volatile("st.release.cta.shared.s32 [%0], %1;" :: "r"(a), "r"(v) : "memory");
}
__device__ __forceinline__ int ld_acquire_shared(const int* p) {
    unsigned a = (unsigned)__cvta_generic_to_shared(p);
    int v;
    asm volatile("ld.acquire.cta.shared.s32 %0, [%1];" : "=r"(v) : "r"(a) : "memory");
    return v;
}

// ---------------------------------------------------------------------------
// GEMM: C[M,N] = A[M,K] @ B[N,K]^T + bias1[n] + bias2[n]
// 128x128 tile, BK=8, 256 threads, 8x8 per-thread microtile. (Proven; unchanged.)
// ---------------------------------------------------------------------------
__global__ void gemm_bias_kernel(const float* __restrict__ A,
                                 const float* __restrict__ B,
                                 float* __restrict__ C,
                                 const float* __restrict__ bias1,
                                 const float* __restrict__ bias2,
                                 int M, int N, int K)
{
    __shared__ float As[8][128];
    __shared__ float Bs[8][128];

    const int tid = threadIdx.x;
    const int bm  = blockIdx.y * 128;
    const int bn  = blockIdx.x * 128;

    const int loadRow = tid >> 1;        // 0..127
    const int loadCol = (tid & 1) * 4;   // 0 or 4

    const int tx = tid & 15;             // n sub-tile
    const int ty = tid >> 4;             // m sub-tile

    float acc[8][8];
#pragma unroll
    for (int i = 0; i < 8; i++)
#pragma unroll
        for (int j = 0; j < 8; j++) acc[i][j] = 0.f;

    const float* Ag = A + (size_t)(bm + loadRow) * K + loadCol;
    const float* Bg = B + (size_t)(bn + loadRow) * K + loadCol;

    for (int k0 = 0; k0 < K; k0 += 8) {
        float4 av = *(const float4*)(Ag + k0);
        float4 bv = *(const float4*)(Bg + k0);
        As[loadCol + 0][loadRow] = av.x;
        As[loadCol + 1][loadRow] = av.y;
        As[loadCol + 2][loadRow] = av.z;
        As[loadCol + 3][loadRow] = av.w;
        Bs[loadCol + 0][loadRow] = bv.x;
        Bs[loadCol + 1][loadRow] = bv.y;
        Bs[loadCol + 2][loadRow] = bv.z;
        Bs[loadCol + 3][loadRow] = bv.w;
        __syncthreads();

#pragma unroll
        for (int k = 0; k < 8; k++) {
            float a[8], b[8];
#pragma unroll
            for (int i = 0; i < 8; i++) a[i] = As[k][ty * 8 + i];
#pragma unroll
            for (int j = 0; j < 8; j++) b[j] = Bs[k][tx * 8 + j];
#pragma unroll
            for (int i = 0; i < 8; i++)
#pragma unroll
                for (int j = 0; j < 8; j++)
                    acc[i][j] += a[i] * b[j];
        }
        __syncthreads();
    }

    // Epilogue with fused bias add, float4 stores
#pragma unroll
    for (int i = 0; i < 8; i++) {
        const int m = bm + ty * 8 + i;
        float* crow = C + (size_t)m * N + bn + tx * 8;
#pragma unroll
        for (int j = 0; j < 8; j += 4) {
            const int n = bn + tx * 8 + j;
            float4 v;
            v.x = acc[i][j + 0] + bias1[n + 0] + bias2[n + 0];
            v.y = acc[i][j + 1] + bias1[n + 1] + bias2[n + 1];
            v.z = acc[i][j + 2] + bias1[n + 2] + bias2[n + 2];
            v.w = acc[i][j + 3] + bias1[n + 3] + bias2[n + 3];
            *(float4*)(crow + j) = v;
        }
    }
}

// ---------------------------------------------------------------------------
// Persistent scan with SPLIT-WAIT: h(t) = tanh(U[t] + Wh @ h(t-1)).
// Wh sliced across 128 CTAs' SMEM (16 rows each, 4 rows per warp).
// Arrival counters split by producer half: LO = CTAs 0-63 (h rows 0-1023),
// HI = CTAs 64-127 (rows 1024-2047). Consumer waits LO, computes the first
// K-half, then checks HI via an early probe that was issued BEFORE the
// first-half compute (usually already satisfied -> tail hidden), then
// computes the second K-half.
// ---------------------------------------------------------------------------
__global__ void __launch_bounds__(SCAN_THREADS, 1)
scan_kernel(const float* __restrict__ Wh,    // layer's H x H row-major slice base
            const float* __restrict__ U,     // S x H (biases already folded in)
            float* __restrict__ Hout,        // S x H; reads t-1, writes t
            int* cnt,                        // split strided arrival counters
            int wait_target)                 // 256*(layer+1) per half
{
    extern __shared__ float smem[];
    float* sW = smem;                         // ROWS_PER_CTA * H_DIM floats
    __shared__ int s_flag;                    // intra-CTA LO relay

    const int tid  = threadIdx.x;
    const int lane = tid & 31;
    const int warp = tid >> 5;
    const int row0 = blockIdx.x * ROWS_PER_CTA;
    // This CTA's arrival target: LO for CTAs 0-63, HI for 64-127
    const int myHalfOff = (blockIdx.x < 64) ? 0 : 64;

    // Stage this CTA's 16 weight rows into SMEM (contiguous rows, coalesced)
    {
        const float4* Wg  = (const float4*)(Wh + (size_t)row0 * H_DIM);
        float4* sW4 = (float4*)sW;
        const int nvec = ROWS_PER_CTA * H_DIM / 4;
        for (int i = tid; i < nvec; i += SCAN_THREADS) sW4[i] = Wg[i];
    }
    if (tid == 0) s_flag = -1;
    __syncthreads();

    const float4* w0 = (const float4*)(sW + (warp * 4 + 0) * H_DIM);
    const float4* w1 = (const float4*)(sW + (warp * 4 + 1) * H_DIM);
    const float4* w2 = (const float4*)(sW + (warp * 4 + 2) * H_DIM);
    const float4* w3 = (const float4*)(sW + (warp * 4 + 3) * H_DIM);

    const int gr0 = row0 + warp * 4;          // this warp's first output row

    for (int t = 0; t < S_LEN; t++) {
        // U is stable data (from the preceding GEMM) — prefetch before wait
        float4 uv;
        if (lane == 0) uv = __ldg((const float4*)(U + (size_t)t * H_DIM + gr0));

        float a0 = 0.f, a1 = 0.f, a2 = 0.f, a3 = 0.f;

        if (t > 0) {
            const int* cLO = cnt + (size_t)(t - 1) * CNT_STRIDE;
            const int* cHI = cLO + 64;

            // ---- wait for LO half (R6-proven: warp0 acquire-spin + relay) ----
            if (warp == 0) {
                while (ld_acquire_gpu(cLO) < wait_target) { }
                if (lane == 0) st_release_shared(&s_flag, t);
            } else {
                while (ld_acquire_shared(&s_flag) < t) { }
            }

            const float4* hp4 = (const float4*)(Hout + (size_t)(t - 1) * H_DIM);

            // Preload the full first K-half (8 float4 per lane = h[0:1024))
            float4 hb[8];
#pragma unroll
            for (int p = 0; p < 8; p++) hb[p] = __ldcg(hp4 + lane + 32 * p);

            // Early HI probe: issued now, inspected after the first-half
            // compute (~512 cyc later) — usually already satisfied.
            int hiSeen = ld_relaxed_gpu(cHI);

            // ---- first K-half: i in [0,8), h rows [0,1024) ----
#pragma unroll
            for (int i = 0; i < 8; i++) {
                const int idx = lane + 32 * i;
                float4 hv = hb[i];
                float4 x0 = w0[idx];
                float4 x1 = w1[idx];
                float4 x2 = w2[idx];
                float4 x3 = w3[idx];
                a0 += x0.x * hv.x + x0.y * hv.y + x0.z * hv.z + x0.w * hv.w;
                a1 += x1.x * hv.x + x1.y * hv.y + x1.z * hv.z + x1.w * hv.w;
                a2 += x2.x * hv.x + x2.y * hv.y + x2.z * hv.z + x2.w * hv.w;
                a3 += x3.x * hv.x + x3.y * hv.y + x3.z * hv.z + x3.w * hv.w;
            }

            // ---- wait for HI half (probe usually satisfied; rare spin) ----
            if (hiSeen < wait_target) {
                while (ld_relaxed_gpu(cHI) < wait_target) { }
            }
            fence_gpu();   // acquire: orders the h[1024:2048) loads below

            // Preload the full second K-half
#pragma unroll
            for (int p = 0; p < 8; p++) hb[p] = __ldcg(hp4 + 256 + lane + 32 * p);

            // ---- second K-half: i in [8,16), h rows [1024,2048) ----
#pragma unroll
            for (int i = 0; i < 8; i++) {
                const int idx = 256 + lane + 32 * i;
                float4 hv = hb[i];
                float4 x0 = w0[idx];
                float4 x1 = w1[idx];
                float4 x2 = w2[idx];
                float4 x3 = w3[idx];
                a0 += x0.x * hv.x + x0.y * hv.y + x0.z * hv.z + x0.w * hv.w;
                a1 += x1.x * hv.x + x1.y * hv.y + x1.z * hv.z + x1.w * hv.w;
                a2 += x2.x * hv.x + x2.y * hv.y + x2.z * hv.z + x2.w * hv.w;
                a3 += x3.x * hv.x + x3.y * hv.y + x3.z * hv.z + x3.w * hv.w;
            }

#pragma unroll
            for (int off = 16; off > 0; off >>= 1) {
                a0 += __shfl_xor_sync(0xffffffffu, a0, off);
                a1 += __shfl_xor_sync(0xffffffffu, a1, off);
                a2 += __shfl_xor_sync(0xffffffffu, a2, off);
                a3 += __shfl_xor_sync(0xffffffffu, a3, off);
            }
        }

        // lane0 holds all four reduced sums: one st.cg.v4 + release-red arrive
        // into this CTA's half counter (release in the storing thread — proven).
        if (lane == 0) {
            float4 hv;
            hv.x = tanhf(uv.x + a0);
            hv.y = tanhf(uv.y + a1);
            hv.z = tanhf(uv.z + a2);
            hv.w = tanhf(uv.w + a3);
            __stcg((float4*)(Hout + (size_t)t * H_DIM + gr0), hv);
            red_release_gpu(cnt + (size_t)t * CNT_STRIDE + myHalfOff);
        }
    }
}

// ---------------------------------------------------------------------------
extern "C" void kernel_launch(void* const* d_in, const int* in_sizes, int n_in,
                              void* d_out, int out_size)
{
    const float* input = (const float*)d_in[0];   // (1, S, I)
    const float* Wi0   = (const float*)d_in[1];   // (H, I)
    const float* bi0   = (const float*)d_in[2];   // (H)
    const float* WiR   = (const float*)d_in[3];   // (L-1, H, H)
    const float* biR   = (const float*)d_in[4];   // (L-1, H)
    const float* Wh    = (const float*)d_in[5];   // (L, H, H)
    const float* bh    = (const float*)d_in[6];   // (L, H)
    float* out = (float*)d_out;                   // (S, 1, H) contiguous

    float *U, *HA; int* cnt;
    cudaGetSymbolAddress((void**)&U,  g_U);
    cudaGetSymbolAddress((void**)&HA, g_HA);
    cudaGetSymbolAddress((void**)&cnt, g_cnt);

    cudaFuncSetAttribute(scan_kernel,
                         cudaFuncAttributeMaxDynamicSharedMemorySize,
                         SCAN_SMEM_BYTES);

    // Counters must be zero at the start of every replay (graph-captured node)
    cudaMemsetAsync(cnt, 0, S_LEN * CNT_STRIDE * sizeof(int));

    dim3 gemm_grid(H_DIM / 128, S_LEN / 128);   // (16, 8)

    // Layer 0: U = X @ Wi0^T + bi0 + bh[0]; then scan with Wh[0]
    gemm_bias_kernel<<<gemm_grid, 256>>>(input, Wi0, U, bi0, bh, S_LEN, H_DIM, I_DIM);
    scan_kernel<<<SCAN_CTAS, SCAN_THREADS, SCAN_SMEM_BYTES>>>(Wh, U, HA, cnt,
                                                              HALF_ARRIVALS);

    // Layers 1..3
    for (int l = 1; l < L_NUM; l++) {
        const float* Wi_l = WiR + (size_t)(l - 1) * H_DIM * H_DIM;
        const float* bi_l = biR + (size_t)(l - 1) * H_DIM;
        const float* Wh_l = Wh  + (size_t)l * H_DIM * H_DIM;
        const float* bh_l = bh  + (size_t)l * H_DIM;
        float* dst = (l == L_NUM - 1) ? out : HA;

        gemm_bias_kernel<<<gemm_grid, 256>>>(HA, Wi_l, U, bi_l, bh_l,
                                             S_LEN, H_DIM, H_DIM);
        scan_kernel<<<SCAN_CTAS, SCAN_THREADS, SCAN_SMEM_BYTES>>>(Wh_l, U, dst, cnt,
                                                                  HALF_ARRIVALS * (l + 1));
    }
}

// round 12
// speedup vs baseline: 1.1860x; 1.1732x over previous
#include <cuda_runtime.h>
#include <math.h>

// Problem constants (fixed by the reference)
#define S_LEN   1024
#define I_DIM   1024
#define H_DIM   2048
#define L_NUM   4

#define SCAN_CTAS     128
#define ROWS_PER_CTA  16              // H_DIM / SCAN_CTAS
#define SCAN_THREADS  256             // 8 warps, 2 rows per warp (2 warps/SMSP)
#define SCAN_SMEM_BYTES (ROWS_PER_CTA * H_DIM * (int)sizeof(float))  // 131072 (weights)
#define CNT_STRIDE 64                 // 256B stride between per-step counters
#define ARRIVALS_PER_STEP SCAN_CTAS   // funneled: ONE red per CTA per step

// Scratch (device globals — no allocation allowed)
__device__ float g_U [S_LEN * H_DIM];            // u_l(t) for current layer (8 MB)
__device__ float g_HA[S_LEN * H_DIM];            // hidden states of current layer (8 MB)
__device__ int   g_cnt[S_LEN * CNT_STRIDE];      // strided per-timestep arrival counters

// ---------------------------------------------------------------------------
// Sync rules banked this session:
//  1. Poll ONLY with morally-strong loads (R4/R7/R8 failed on weak ld.cg).
//  2. ONE warp polls globally per CTA; relay intra-CTA via SMEM
//     (R6 12.3ms vs R5/R9 all-warp polling 15.1ms).
//  3. Release fence must execute in the STORING thread (R4 failure).
// Wait side below is byte-pattern R6 (proven). Commit side is R2-proven
// (st.cg -> fence in storer -> barrier -> single arrival red).
// ---------------------------------------------------------------------------
__device__ __forceinline__ int ld_acquire_gpu(const int* p) {
    int v;
    asm volatile("ld.acquire.gpu.global.s32 %0, [%1];" : "=r"(v) : "l"(p) : "memory");
    return v;
}
__device__ __forceinline__ void fence_gpu() {
    asm volatile("fence.acq_rel.gpu;" ::: "memory");
}
__device__ __forceinline__ void red_release_gpu(int* p) {
    asm volatile("red.release.gpu.global.add.s32 [%0], 1;" :: "l"(p) : "memory");
}
__device__ __forceinline__ void st_release_shared(int* p, int v) {
    unsigned a = (unsigned)__cvta_generic_to_shared(p);
    asm volatile("st.release.cta.shared.s32 [%0], %1;" :: "r"(a), "r"(v) : "memory");
}
__device__ __forceinline__ int ld_acquire_shared(const int* p) {
    unsigned a = (unsigned)__cvta_generic_to_shared(p);
    int v;
    asm volatile("ld.acquire.cta.shared.s32 %0, [%1];" : "=r"(v) : "r"(a) : "memory");
    return v;
}

// ---------------------------------------------------------------------------
// GEMM: C[M,N] = A[M,K] @ B[N,K]^T + bias1[n] + bias2[n]
// 128x128 tile, BK=8, 256 threads, 8x8 per-thread microtile. (Proven; unchanged.)
// ---------------------------------------------------------------------------
__global__ void gemm_bias_kernel(const float* __restrict__ A,
                                 const float* __restrict__ B,
                                 float* __restrict__ C,
                                 const float* __restrict__ bias1,
                                 const float* __restrict__ bias2,
                                 int M, int N, int K)
{
    __shared__ float As[8][128];
    __shared__ float Bs[8][128];

    const int tid = threadIdx.x;
    const int bm  = blockIdx.y * 128;
    const int bn  = blockIdx.x * 128;

    const int loadRow = tid >> 1;        // 0..127
    const int loadCol = (tid & 1) * 4;   // 0 or 4

    const int tx = tid & 15;             // n sub-tile
    const int ty = tid >> 4;             // m sub-tile

    float acc[8][8];
#pragma unroll
    for (int i = 0; i < 8; i++)
#pragma unroll
        for (int j = 0; j < 8; j++) acc[i][j] = 0.f;

    const float* Ag = A + (size_t)(bm + loadRow) * K + loadCol;
    const float* Bg = B + (size_t)(bn + loadRow) * K + loadCol;

    for (int k0 = 0; k0 < K; k0 += 8) {
        float4 av = *(const float4*)(Ag + k0);
        float4 bv = *(const float4*)(Bg + k0);
        As[loadCol + 0][loadRow] = av.x;
        As[loadCol + 1][loadRow] = av.y;
        As[loadCol + 2][loadRow] = av.z;
        As[loadCol + 3][loadRow] = av.w;
        Bs[loadCol + 0][loadRow] = bv.x;
        Bs[loadCol + 1][loadRow] = bv.y;
        Bs[loadCol + 2][loadRow] = bv.z;
        Bs[loadCol + 3][loadRow] = bv.w;
        __syncthreads();

#pragma unroll
        for (int k = 0; k < 8; k++) {
            float a[8], b[8];
#pragma unroll
            for (int i = 0; i < 8; i++) a[i] = As[k][ty * 8 + i];
#pragma unroll
            for (int j = 0; j < 8; j++) b[j] = Bs[k][tx * 8 + j];
#pragma unroll
            for (int i = 0; i < 8; i++)
#pragma unroll
                for (int j = 0; j < 8; j++)
                    acc[i][j] += a[i] * b[j];
        }
        __syncthreads();
    }

    // Epilogue with fused bias add, float4 stores
#pragma unroll
    for (int i = 0; i < 8; i++) {
        const int m = bm + ty * 8 + i;
        float* crow = C + (size_t)m * N + bn + tx * 8;
#pragma unroll
        for (int j = 0; j < 8; j += 4) {
            const int n = bn + tx * 8 + j;
            float4 v;
            v.x = acc[i][j + 0] + bias1[n + 0] + bias2[n + 0];
            v.y = acc[i][j + 1] + bias1[n + 1] + bias2[n + 1];
            v.z = acc[i][j + 2] + bias1[n + 2] + bias2[n + 2];
            v.w = acc[i][j + 3] + bias1[n + 3] + bias2[n + 3];
            *(float4*)(crow + j) = v;
        }
    }
}

// ---------------------------------------------------------------------------
// Persistent scan: h(t) = tanh(U[t] + Wh @ h(t-1)) over t = 0..S-1.
// Wh sliced across 128 CTAs' SMEM (16 rows each). 8 warps per CTA,
// 2 rows per warp -> 2 warps per SMSP to hide LDS/LDG latency.
// Per step:
//   wait:   warp0 acquire-polls cnt[t-1] (R6-proven), relays via s_flag
//           (st.release.cta / ld.acquire.cta) to warps 1-7.
//   compute: each warp dot-products its 2 rows against h(t-1) streamed
//           from L2 via the depth-8 __ldcg rolling pipeline.
//   commit (funneled, ONE red per CTA): warps STS their 2 row-sums to
//           s_res -> __syncthreads -> warp0 lanes 0-15 tanh+st.cg their
//           row, fence IN the storing thread (R2-proven), __syncwarp,
//           lane0 red.release on cnt[t]. 128 arrivals/step chip-wide.
// s_res reuse is race-free: warps can only write s_res for step t+1 after
// passing the s_flag wait for t+1, which warp0 publishes after it has
// finished reading s_res for step t.
// ---------------------------------------------------------------------------
__global__ void __launch_bounds__(SCAN_THREADS, 1)
scan_kernel(const float* __restrict__ Wh,    // layer's H x H row-major slice base
            const float* __restrict__ U,     // S x H (biases already folded in)
            float* __restrict__ Hout,        // S x H; reads t-1, writes t
            int* cnt,                        // strided arrival counters
            int wait_target)                 // 128*(layer+1)
{
    extern __shared__ float smem[];
    float* sW = smem;                         // ROWS_PER_CTA * H_DIM floats
    __shared__ float s_res[ROWS_PER_CTA];     // per-row partial sums (funnel)
    __shared__ int   s_flag;                  // intra-CTA step relay (monotonic)

    const int tid  = threadIdx.x;
    const int lane = tid & 31;
    const int warp = tid >> 5;                // 0..7
    const int row0 = blockIdx.x * ROWS_PER_CTA;

    // Stage this CTA's 16 weight rows into SMEM (contiguous rows, coalesced)
    {
        const float4* Wg  = (const float4*)(Wh + (size_t)row0 * H_DIM);
        float4* sW4 = (float4*)sW;
        const int nvec = ROWS_PER_CTA * H_DIM / 4;
        for (int i = tid; i < nvec; i += SCAN_THREADS) sW4[i] = Wg[i];
    }
    if (tid == 0) s_flag = 0;
    __syncthreads();

    const float4* w0 = (const float4*)(sW + (warp * 2 + 0) * H_DIM);
    const float4* w1 = (const float4*)(sW + (warp * 2 + 1) * H_DIM);

    for (int t = 0; t < S_LEN; t++) {
        // warp0 preloads U for all 16 rows of this CTA (stable data, before wait)
        float uval = 0.f;
        if (warp == 0 && lane < ROWS_PER_CTA)
            uval = __ldg(U + (size_t)t * H_DIM + row0 + lane);

        float a0 = 0.f, a1 = 0.f;

        if (t > 0) {
            if (warp == 0) {
                while (ld_acquire_gpu(cnt + (size_t)(t - 1) * CNT_STRIDE) < wait_target) { }
                if (lane == 0) st_release_shared(&s_flag, t);
            } else {
                while (ld_acquire_shared(&s_flag) < t) { }
            }

            // h(t-1): depth-8 register-rolling __ldcg pipeline (R6-proven)
            const float4* hp4 = (const float4*)(Hout + (size_t)(t - 1) * H_DIM);
            float4 hb[8];
#pragma unroll
            for (int p = 0; p < 8; p++) hb[p] = __ldcg(hp4 + lane + 32 * p);

#pragma unroll
            for (int i = 0; i < H_DIM / 128; i++) {     // 16 iterations
                const int idx = lane + 32 * i;
                float4 hv = hb[i & 7];
                if (i + 8 < H_DIM / 128)
                    hb[i & 7] = __ldcg(hp4 + idx + 32 * 8);
                float4 x0 = w0[idx];
                float4 x1 = w1[idx];
                a0 += x0.x * hv.x + x0.y * hv.y + x0.z * hv.z + x0.w * hv.w;
                a1 += x1.x * hv.x + x1.y * hv.y + x1.z * hv.z + x1.w * hv.w;
            }
#pragma unroll
            for (int off = 16; off > 0; off >>= 1) {
                a0 += __shfl_xor_sync(0xffffffffu, a0, off);
                a1 += __shfl_xor_sync(0xffffffffu, a1, off);
            }
        }

        // Funnel: lanes 0,1 of each warp park their row-sums in SMEM
        if (lane < 2) s_res[warp * 2 + lane] = (lane == 0) ? a0 : a1;
        __syncthreads();   // all partials visible to warp0

        // warp0 finishes: tanh + store + fence in the STORING thread, then
        // one release-red for the whole CTA.
        if (warp == 0) {
            if (lane < ROWS_PER_CTA) {
                const float v = tanhf(uval + s_res[lane]);
                __stcg(Hout + (size_t)t * H_DIM + row0 + lane, v);
                fence_gpu();                    // R2-proven: fence by the storer
            }
            __syncwarp();
            if (lane == 0) red_release_gpu(cnt + (size_t)t * CNT_STRIDE);
        }
    }
}

// ---------------------------------------------------------------------------
extern "C" void kernel_launch(void* const* d_in, const int* in_sizes, int n_in,
                              void* d_out, int out_size)
{
    const float* input = (const float*)d_in[0];   // (1, S, I)
    const float* Wi0   = (const float*)d_in[1];   // (H, I)
    const float* bi0   = (const float*)d_in[2];   // (H)
    const float* WiR   = (const float*)d_in[3];   // (L-1, H, H)
    const float* biR   = (const float*)d_in[4];   // (L-1, H)
    const float* Wh    = (const float*)d_in[5];   // (L, H, H)
    const float* bh    = (const float*)d_in[6];   // (L, H)
    float* out = (float*)d_out;                   // (S, 1, H) contiguous

    float *U, *HA; int* cnt;
    cudaGetSymbolAddress((void**)&U,  g_U);
    cudaGetSymbolAddress((void**)&HA, g_HA);
    cudaGetSymbolAddress((void**)&cnt, g_cnt);

    cudaFuncSetAttribute(scan_kernel,
                         cudaFuncAttributeMaxDynamicSharedMemorySize,
                         SCAN_SMEM_BYTES);

    // Counters must be zero at the start of every replay (graph-captured node)
    cudaMemsetAsync(cnt, 0, S_LEN * CNT_STRIDE * sizeof(int));

    dim3 gemm_grid(H_DIM / 128, S_LEN / 128);   // (16, 8)

    // Layer 0: U = X @ Wi0^T + bi0 + bh[0]; then scan with Wh[0]
    gemm_bias_kernel<<<gemm_grid, 256>>>(input, Wi0, U, bi0, bh, S_LEN, H_DIM, I_DIM);
    scan_kernel<<<SCAN_CTAS, SCAN_THREADS, SCAN_SMEM_BYTES>>>(Wh, U, HA, cnt,
                                                              ARRIVALS_PER_STEP);

    // Layers 1..3
    for (int l = 1; l < L_NUM; l++) {
        const float* Wi_l = WiR + (size_t)(l - 1) * H_DIM * H_DIM;
        const float* bi_l = biR + (size_t)(l - 1) * H_DIM;
        const float* Wh_l = Wh  + (size_t)l * H_DIM * H_DIM;
        const float* bh_l = bh  + (size_t)l * H_DIM;
        float* dst = (l == L_NUM - 1) ? out : HA;

        gemm_bias_kernel<<<gemm_grid, 256>>>(HA, Wi_l, U, bi_l, bh_l,
                                             S_LEN, H_DIM, H_DIM);
        scan_kernel<<<SCAN_CTAS, SCAN_THREADS, SCAN_SMEM_BYTES>>>(Wh_l, U, dst, cnt,
                                                                  ARRIVALS_PER_STEP * (l + 1));
    }
}

// round 14
// speedup vs baseline: 1.2641x; 1.0659x over previous
#include <cuda_runtime.h>
#include <math.h>

// Problem constants (fixed by the reference)
#define S_LEN   1024
#define I_DIM   1024
#define H_DIM   2048
#define L_NUM   4

#define SCAN_CTAS     128
#define ROWS_PER_CTA  16              // H_DIM / SCAN_CTAS
#define SCAN_THREADS  256             // 8 warps: 2 row-groups x 4 K-slices
#define SCAN_SMEM_BYTES (ROWS_PER_CTA * H_DIM * (int)sizeof(float))  // 131072 (weights)
#define CNT_STRIDE 64                 // 256B stride between per-step counters
#define ARRIVALS_PER_STEP SCAN_CTAS   // funneled: ONE red per CTA per step

// Scratch (device globals — no allocation allowed)
__device__ float g_U [S_LEN * H_DIM];            // u_l(t) for current layer (8 MB)
__device__ float g_HA[S_LEN * H_DIM];            // hidden states of current layer (8 MB)
__device__ int   g_cnt[S_LEN * CNT_STRIDE];      // strided per-timestep arrival counters

// ---------------------------------------------------------------------------
// Sync rules banked this session:
//  1. Poll ONLY with morally-strong loads (R4/R7/R8 failed on weak ld.cg).
//  2. ONE warp polls globally per CTA; relay intra-CTA via SMEM
//     (R6 12.3ms vs R5/R9 all-warp polling 15.1ms).
//  3. Release fence must execute in the STORING thread (R4 failure).
//  4. (R12 vs R6): per-warp full-H h loads put 4-8 MB/step through L2 —
//     that, not the protocol, is the hidden cost. This round K-splits warps
//     so each loads a 2KB chunk: 2 MB/step total.
// ---------------------------------------------------------------------------
__device__ __forceinline__ int ld_acquire_gpu(const int* p) {
    int v;
    asm volatile("ld.acquire.gpu.global.s32 %0, [%1];" : "=r"(v) : "l"(p) : "memory");
    return v;
}
__device__ __forceinline__ void fence_gpu() {
    asm volatile("fence.acq_rel.gpu;" ::: "memory");
}
__device__ __forceinline__ void red_release_gpu(int* p) {
    asm volatile("red.release.gpu.global.add.s32 [%0], 1;" :: "l"(p) : "memory");
}
__device__ __forceinline__ void st_release_shared(int* p, int v) {
    unsigned a = (unsigned)__cvta_generic_to_shared(p);
    asm volatile("st.release.cta.shared.s32 [%0], %1;" :: "r"(a), "r"(v) : "memory");
}
__device__ __forceinline__ int ld_acquire_shared(const int* p) {
    unsigned a = (unsigned)__cvta_generic_to_shared(p);
    int v;
    asm volatile("ld.acquire.cta.shared.s32 %0, [%1];" : "=r"(v) : "r"(a) : "memory");
    return v;
}

// ---------------------------------------------------------------------------
// GEMM: C[M,N] = A[M,K] @ B[N,K]^T + bias1[n] + bias2[n]
// 128x128 tile, BK=8, 256 threads, 8x8 per-thread microtile. (Proven; unchanged.)
// ---------------------------------------------------------------------------
__global__ void gemm_bias_kernel(const float* __restrict__ A,
                                 const float* __restrict__ B,
                                 float* __restrict__ C,
                                 const float* __restrict__ bias1,
                                 const float* __restrict__ bias2,
                                 int M, int N, int K)
{
    __shared__ float As[8][128];
    __shared__ float Bs[8][128];

    const int tid = threadIdx.x;
    const int bm  = blockIdx.y * 128;
    const int bn  = blockIdx.x * 128;

    const int loadRow = tid >> 1;        // 0..127
    const int loadCol = (tid & 1) * 4;   // 0 or 4

    const int tx = tid & 15;             // n sub-tile
    const int ty = tid >> 4;             // m sub-tile

    float acc[8][8];
#pragma unroll
    for (int i = 0; i < 8; i++)
#pragma unroll
        for (int j = 0; j < 8; j++) acc[i][j] = 0.f;

    const float* Ag = A + (size_t)(bm + loadRow) * K + loadCol;
    const float* Bg = B + (size_t)(bn + loadRow) * K + loadCol;

    for (int k0 = 0; k0 < K; k0 += 8) {
        float4 av = *(const float4*)(Ag + k0);
        float4 bv = *(const float4*)(Bg + k0);
        As[loadCol + 0][loadRow] = av.x;
        As[loadCol + 1][loadRow] = av.y;
        As[loadCol + 2][loadRow] = av.z;
        As[loadCol + 3][loadRow] = av.w;
        Bs[loadCol + 0][loadRow] = bv.x;
        Bs[loadCol + 1][loadRow] = bv.y;
        Bs[loadCol + 2][loadRow] = bv.z;
        Bs[loadCol + 3][loadRow] = bv.w;
        __syncthreads();

#pragma unroll
        for (int k = 0; k < 8; k++) {
            float a[8], b[8];
#pragma unroll
            for (int i = 0; i < 8; i++) a[i] = As[k][ty * 8 + i];
#pragma unroll
            for (int j = 0; j < 8; j++) b[j] = Bs[k][tx * 8 + j];
#pragma unroll
            for (int i = 0; i < 8; i++)
#pragma unroll
                for (int j = 0; j < 8; j++)
                    acc[i][j] += a[i] * b[j];
        }
        __syncthreads();
    }

    // Epilogue with fused bias add, float4 stores
#pragma unroll
    for (int i = 0; i < 8; i++) {
        const int m = bm + ty * 8 + i;
        float* crow = C + (size_t)m * N + bn + tx * 8;
#pragma unroll
        for (int j = 0; j < 8; j += 4) {
            const int n = bn + tx * 8 + j;
            float4 v;
            v.x = acc[i][j + 0] + bias1[n + 0] + bias2[n + 0];
            v.y = acc[i][j + 1] + bias1[n + 1] + bias2[n + 1];
            v.z = acc[i][j + 2] + bias1[n + 2] + bias2[n + 2];
            v.w = acc[i][j + 3] + bias1[n + 3] + bias2[n + 3];
            *(float4*)(crow + j) = v;
        }
    }
}

// ---------------------------------------------------------------------------
// Persistent scan, K-SPLIT: h(t) = tanh(U[t] + Wh @ h(t-1)).
// Wh sliced across 128 CTAs' SMEM (16 rows each). 8 warps per CTA arranged
// as 2 row-groups x 4 K-slices: warp w owns rows [8*(w>>2),+8) over
// K in [512*(w&3), +512). Each warp loads only its 2KB h-chunk ->
// h L2 traffic = 2MB/step chip-wide (was 8MB in R12, 4MB in R6).
// Per step:
//   wait:   warp0 acquire-polls cnt[t-1], relays via s_flag (R6-proven).
//   load:   4 ldcg float4 per lane, issued upfront (one L2 round trip).
//   compute: 4 iters x (8 rows LDS.128 + 32 FFMA). SM total 256 LDS.128
//            = the 1024-cyc floor; 2 warps/SMSP hide latency.
//   reduce: 8 shfl-reduced accums -> lanes 0-7 STS into s_part[kslice][row]
//           -> __syncthreads -> warp0 lanes 0-15 sum 4 partials + tanh +
//           st.cg + fence in storer + ONE red.release per CTA (R12-proven).
// s_part reuse race-free: warps write step t+1 partials only after the
// relay for t+1, which warp0 publishes after reading s_part for step t.
// ---------------------------------------------------------------------------
__global__ void __launch_bounds__(SCAN_THREADS, 1)
scan_kernel(const float* __restrict__ Wh,    // layer's H x H row-major slice base
            const float* __restrict__ U,     // S x H (biases already folded in)
            float* __restrict__ Hout,        // S x H; reads t-1, writes t
            int* cnt,                        // strided arrival counters
            int wait_target)                 // 128*(layer+1)
{
    extern __shared__ float smem[];
    float* sW = smem;                         // ROWS_PER_CTA * H_DIM floats
    __shared__ float s_part[4 * ROWS_PER_CTA];// partials: [kslice][row]
    __shared__ int   s_flag;                  // intra-CTA step relay (monotonic)

    const int tid  = threadIdx.x;
    const int lane = tid & 31;
    const int warp = tid >> 5;                // 0..7
    const int rgrp = warp >> 2;               // 0..1 (row group)
    const int ksl  = warp & 3;                // 0..3 (K slice)
    const int row0 = blockIdx.x * ROWS_PER_CTA;
    const int r0   = rgrp * 8;                // first local row of this warp
    const int kq   = ksl * 128;               // K-chunk base in float4 units (512 floats)

    // Stage this CTA's 16 weight rows into SMEM (contiguous rows, coalesced)
    {
        const float4* Wg  = (const float4*)(Wh + (size_t)row0 * H_DIM);
        float4* sW4 = (float4*)sW;
        const int nvec = ROWS_PER_CTA * H_DIM / 4;
        for (int i = tid; i < nvec; i += SCAN_THREADS) sW4[i] = Wg[i];
    }
    if (tid == 0) s_flag = 0;
    __syncthreads();

    // Per-warp weight row pointers (float4), offset to this warp's K-chunk
    const float4* wr[8];
#pragma unroll
    for (int j = 0; j < 8; j++)
        wr[j] = (const float4*)(sW + (size_t)(r0 + j) * H_DIM) + kq;

    for (int t = 0; t < S_LEN; t++) {
        // warp0 preloads U for all 16 rows (stable data, before the wait)
        float uval = 0.f;
        if (warp == 0 && lane < ROWS_PER_CTA)
            uval = __ldg(U + (size_t)t * H_DIM + row0 + lane);

        float a0 = 0.f, a1 = 0.f, a2 = 0.f, a3 = 0.f;
        float a4 = 0.f, a5 = 0.f, a6 = 0.f, a7 = 0.f;

        if (t > 0) {
            if (warp == 0) {
                while (ld_acquire_gpu(cnt + (size_t)(t - 1) * CNT_STRIDE) < wait_target) { }
                if (lane == 0) st_release_shared(&s_flag, t);
            } else {
                while (ld_acquire_shared(&s_flag) < t) { }
            }

            // This warp's 2KB h-chunk: 4 float4 per lane, all in flight at once
            const float4* hp4 = (const float4*)(Hout + (size_t)(t - 1) * H_DIM) + kq;
            float4 hb0 = __ldcg(hp4 + lane);
            float4 hb1 = __ldcg(hp4 + lane + 32);
            float4 hb2 = __ldcg(hp4 + lane + 64);
            float4 hb3 = __ldcg(hp4 + lane + 96);

#pragma unroll
            for (int i = 0; i < 4; i++) {
                const float4 hv = (i == 0) ? hb0 : (i == 1) ? hb1
                                : (i == 2) ? hb2 : hb3;
                const int idx = lane + 32 * i;
                float4 x;
                x = wr[0][idx]; a0 += x.x*hv.x + x.y*hv.y + x.z*hv.z + x.w*hv.w;
                x = wr[1][idx]; a1 += x.x*hv.x + x.y*hv.y + x.z*hv.z + x.w*hv.w;
                x = wr[2][idx]; a2 += x.x*hv.x + x.y*hv.y + x.z*hv.z + x.w*hv.w;
                x = wr[3][idx]; a3 += x.x*hv.x + x.y*hv.y + x.z*hv.z + x.w*hv.w;
                x = wr[4][idx]; a4 += x.x*hv.x + x.y*hv.y + x.z*hv.z + x.w*hv.w;
                x = wr[5][idx]; a5 += x.x*hv.x + x.y*hv.y + x.z*hv.z + x.w*hv.w;
                x = wr[6][idx]; a6 += x.x*hv.x + x.y*hv.y + x.z*hv.z + x.w*hv.w;
                x = wr[7][idx]; a7 += x.x*hv.x + x.y*hv.y + x.z*hv.z + x.w*hv.w;
            }
#pragma unroll
            for (int off = 16; off > 0; off >>= 1) {
                a0 += __shfl_xor_sync(0xffffffffu, a0, off);
                a1 += __shfl_xor_sync(0xffffffffu, a1, off);
                a2 += __shfl_xor_sync(0xffffffffu, a2, off);
                a3 += __shfl_xor_sync(0xffffffffu, a3, off);
                a4 += __shfl_xor_sync(0xffffffffu, a4, off);
                a5 += __shfl_xor_sync(0xffffffffu, a5, off);
                a6 += __shfl_xor_sync(0xffffffffu, a6, off);
                a7 += __shfl_xor_sync(0xffffffffu, a7, off);
            }
        }

        // lanes 0-7 park this warp's 8 row-partials in SMEM
        if (lane < 8) {
            const float v = (lane == 0) ? a0 : (lane == 1) ? a1
                          : (lane == 2) ? a2 : (lane == 3) ? a3
                          : (lane == 4) ? a4 : (lane == 5) ? a5
                          : (lane == 6) ? a6 : a7;
            s_part[ksl * ROWS_PER_CTA + r0 + lane] = v;
        }
        __syncthreads();   // all partials visible to warp0

        // warp0 funnel: sum 4 K-slices, tanh, store, fence in storer, one red
        if (warp == 0) {
            if (lane < ROWS_PER_CTA) {
                const float s = s_part[lane]
                              + s_part[ROWS_PER_CTA + lane]
                              + s_part[2 * ROWS_PER_CTA + lane]
                              + s_part[3 * ROWS_PER_CTA + lane];
                __stcg(Hout + (size_t)t * H_DIM + row0 + lane, tanhf(uval + s));
                fence_gpu();                    // R2-proven: fence by the storer
            }
            __syncwarp();
            if (lane == 0) red_release_gpu(cnt + (size_t)t * CNT_STRIDE);
        }
    }
}

// ---------------------------------------------------------------------------
extern "C" void kernel_launch(void* const* d_in, const int* in_sizes, int n_in,
                              void* d_out, int out_size)
{
    const float* input = (const float*)d_in[0];   // (1, S, I)
    const float* Wi0   = (const float*)d_in[1];   // (H, I)
    const float* bi0   = (const float*)d_in[2];   // (H)
    const float* WiR   = (const float*)d_in[3];   // (L-1, H, H)
    const float* biR   = (const float*)d_in[4];   // (L-1, H)
    const float* Wh    = (const float*)d_in[5];   // (L, H, H)
    const float* bh    = (const float*)d_in[6];   // (L, H)
    float* out = (float*)d_out;                   // (S, 1, H) contiguous

    float *U, *HA; int* cnt;
    cudaGetSymbolAddress((void**)&U,  g_U);
    cudaGetSymbolAddress((void**)&HA, g_HA);
    cudaGetSymbolAddress((void**)&cnt, g_cnt);

    cudaFuncSetAttribute(scan_kernel,
                         cudaFuncAttributeMaxDynamicSharedMemorySize,
                         SCAN_SMEM_BYTES);

    // Counters must be zero at the start of every replay (graph-captured node)
    cudaMemsetAsync(cnt, 0, S_LEN * CNT_STRIDE * sizeof(int));

    dim3 gemm_grid(H_DIM / 128, S_LEN / 128);   // (16, 8)

    // Layer 0: U = X @ Wi0^T + bi0 + bh[0]; then scan with Wh[0]
    gemm_bias_kernel<<<gemm_grid, 256>>>(input, Wi0, U, bi0, bh, S_LEN, H_DIM, I_DIM);
    scan_kernel<<<SCAN_CTAS, SCAN_THREADS, SCAN_SMEM_BYTES>>>(Wh, U, HA, cnt,
                                                              ARRIVALS_PER_STEP);

    // Layers 1..3
    for (int l = 1; l < L_NUM; l++) {
        const float* Wi_l = WiR + (size_t)(l - 1) * H_DIM * H_DIM;
        const float* bi_l = biR + (size_t)(l - 1) * H_DIM;
        const float* Wh_l = Wh  + (size_t)l * H_DIM * H_DIM;
        const float* bh_l = bh  + (size_t)l * H_DIM;
        float* dst = (l == L_NUM - 1) ? out : HA;

        gemm_bias_kernel<<<gemm_grid, 256>>>(HA, Wi_l, U, bi_l, bh_l,
                                             S_LEN, H_DIM, H_DIM);
        scan_kernel<<<SCAN_CTAS, SCAN_THREADS, SCAN_SMEM_BYTES>>>(Wh_l, U, dst, cnt,
                                                                  ARRIVALS_PER_STEP * (l + 1));
    }
}